// round 3
// baseline (speedup 1.0000x reference)
#include <cuda_runtime.h>
#include <math.h>

#define Bb 32
#define Tt 8
#define Nn 150
#define Ff 16
#define Hh 32
#define Rr 4
#define Ee 16

#define BNH  (Bb*Nn*Hh)
#define BNHR (BNH*Rr)
#define OUTE (Bb*Tt*Nn*Hh*Rr)

// ---------------- device state (allocation-free scratch) ----------------
__device__ float4 g_Af[Nn*Nn];          // spectral adjacency planes
__device__ float  g_adj[Nn*Nn*Rr];      // time-domain adj (relu -> softmax in place)
__device__ float4 g_Wf[10][Hh*Hh];      // spectral weights (layer0: 0..4, layer1: 5..9)
__device__ float  g_h0[2][BNHR];        // layer0 hidden double buffer
__device__ float  g_h1[2][BNHR];        // layer1 hidden double buffer
__device__ float  g_zb[BNHR];           // zeros
__device__ float4 g_Xf[BNH];
__device__ float4 g_Hf[BNH];
__device__ float4 g_AXf[BNH];
__device__ float4 g_AHf[BNH];
__device__ float4 g_Gf[BNH];
__device__ float4 g_RHf[BNH];
__device__ float4 g_ARHf[BNH];
__device__ float  g_Z[BNHR];

// ---------------- 4-point FFT helpers (jnp.fft convention) ----------------
// planes: (X0, Re X1, Im X1, X2); X1 = x0 - i x1 - x2 + i x3
__device__ __forceinline__ float4 fft4(float x0, float x1, float x2, float x3) {
    return make_float4(x0 + x1 + x2 + x3, x0 - x2, x3 - x1, x0 - x1 + x2 - x3);
}
__device__ __forceinline__ void ifft4(float4 s, float* x) {
    x[0] = 0.25f * (s.x + 2.f * s.y + s.w);
    x[1] = 0.25f * (s.x - 2.f * s.z - s.w);
    x[2] = 0.25f * (s.x - 2.f * s.y + s.w);
    x[3] = 0.25f * (s.x + 2.f * s.z - s.w);
}
// facewise product accumulate: o += a (*) x  (per-frequency complex mult)
__device__ __forceinline__ void cacc(float4& o, float4 a, float4 x) {
    o.x += a.x * x.x;
    o.y += a.y * x.y - a.z * x.z;
    o.z += a.y * x.z + a.z * x.y;
    o.w += a.w * x.w;
}

__device__ __forceinline__ float* hbuf(int sel) {
    switch (sel) {
        case 1: return g_h0[0];
        case 2: return g_h0[1];
        case 3: return g_h1[0];
        case 4: return g_h1[1];
        default: return g_zb;
    }
}

// ---------------- precompute kernels ----------------
__global__ void k_zero() {
    int i = blockIdx.x * blockDim.x + threadIdx.x;
    if (i < BNHR) g_zb[i] = 0.f;
}

// A_raw = relu( Re ifft( sum_e fft(U[n,e,:]) * fft(U[m,e,:]) ) )
__global__ void k_adj_raw(const float* __restrict__ U) {
    int idx = blockIdx.x * blockDim.x + threadIdx.x;
    if (idx >= Nn * Nn) return;
    int n = idx / Nn, m = idx % Nn;
    float4 g = make_float4(0.f, 0.f, 0.f, 0.f);
    for (int e = 0; e < Ee; e++) {
        const float* un = U + (n * Ee + e) * Rr;
        const float* um = U + (m * Ee + e) * Rr;
        float4 a = fft4(un[0], un[1], un[2], un[3]);
        float4 b = fft4(um[0], um[1], um[2], um[3]);
        cacc(g, a, b);
    }
    float x[4];
    ifft4(g, x);
    #pragma unroll
    for (int r = 0; r < 4; r++) g_adj[idx * 4 + r] = fmaxf(x[r], 0.f);
}

// softmax over m (axis=1) for each (n, r)
__global__ void k_softmax() {
    int n = blockIdx.x, r = blockIdx.y;
    int tid = threadIdx.x;
    __shared__ float red[256];
    float v = (tid < Nn) ? g_adj[(n * Nn + tid) * Rr + r] : -1e30f;
    red[tid] = v;
    __syncthreads();
    for (int s = 128; s > 0; s >>= 1) {
        if (tid < s) red[tid] = fmaxf(red[tid], red[tid + s]);
        __syncthreads();
    }
    float mx = red[0];
    __syncthreads();
    float e = (tid < Nn) ? expf(v - mx) : 0.f;
    red[tid] = e;
    __syncthreads();
    for (int s = 128; s > 0; s >>= 1) {
        if (tid < s) red[tid] += red[tid + s];
        __syncthreads();
    }
    float inv = 1.f / red[0];
    if (tid < Nn) g_adj[(n * Nn + tid) * Rr + r] = e * inv;
}

__global__ void k_adj_fft() {
    int idx = blockIdx.x * blockDim.x + threadIdx.x;
    if (idx >= Nn * Nn) return;
    const float* a = g_adj + idx * 4;
    g_Af[idx] = fft4(a[0], a[1], a[2], a[3]);
}

__global__ void k_wfft(const float* __restrict__ W, int wi, int sz) {
    int idx = blockIdx.x * blockDim.x + threadIdx.x;
    if (idx >= sz) return;
    const float* w = W + idx * Rr;
    g_Wf[wi][idx] = fft4(w[0], w[1], w[2], w[3]);
}

// ---------------- per-cell kernels ----------------
// fft of X input and hidden state into float4 spectral layout [b][node][chan]
__global__ void k_pre(const float* __restrict__ xb_in, int xsel, int xsB, int Fin, int hsel) {
    int idx = blockIdx.x * blockDim.x + threadIdx.x;
    int nx = Bb * Nn * Fin;
    if (idx < nx) {
        const float* xb = xsel ? hbuf(xsel) : xb_in;
        int f = idx % Fin;
        int n = (idx / Fin) % Nn;
        int b = idx / (Fin * Nn);
        const float* p = xb + b * xsB + (n * Fin + f) * Rr;
        g_Xf[(b * Nn + n) * Fin + f] = fft4(p[0], p[1], p[2], p[3]);
    } else {
        int j = idx - nx;
        if (j >= BNH) return;
        const float* p = hbuf(hsel) + j * Rr;
        g_Hf[j] = fft4(p[0], p[1], p[2], p[3]);
    }
}

// facewise aggregation out[b,n,c] = sum_m Af[n,m] (*) in[b,m,c]
// mode 0: gridDim.z=2 -> z=0: Xf->AXf (C=C0), z=1: Hf->AHf (C=Hh)
// mode 1: RHf->ARHf (C=Hh)
__global__ void k_agg(int mode, int C0) {
    const float4* in;
    float4* out;
    int C;
    if (mode == 0) {
        if (blockIdx.z == 0) { in = g_Xf; out = g_AXf; C = C0; }
        else                 { in = g_Hf; out = g_AHf; C = Hh; }
    } else {
        in = g_RHf; out = g_ARHf; C = Hh;
    }
    int c = threadIdx.x;
    int n = blockIdx.x * blockDim.y + threadIdx.y;
    int b = blockIdx.y;
    if (n >= Nn || c >= C) return;
    const float4* xb = in + b * Nn * C;
    const float4* ar = g_Af + n * Nn;
    float4 acc = make_float4(0.f, 0.f, 0.f, 0.f);
    #pragma unroll 2
    for (int m = 0; m < Nn; m++) {
        float4 a = ar[m];
        float4 x = xb[m * C + c];
        cacc(acc, a, x);
    }
    out[(b * Nn + n) * C + c] = acc;
}

// Z, R gates + stash spectral G = AXf@Wxh and RHf = fft(R * Hs)
__global__ void k_zr(int Fin, int wz, int wr, int wh, int whz, int whr,
                     const float* __restrict__ bias, int hsel) {
    int idx = blockIdx.x * blockDim.x + threadIdx.x;
    if (idx >= BNH) return;
    int h = idx % Hh;
    int bn = idx / Hh;
    const float4* Wxz = g_Wf[wz];
    const float4* Wxr = g_Wf[wr];
    const float4* Wxh = g_Wf[wh];
    const float4* Whz = g_Wf[whz];
    const float4* Whr = g_Wf[whr];

    float4 zf = make_float4(0.f, 0.f, 0.f, 0.f);
    float4 rf = zf, gf = zf;
    const float4* ax = g_AXf + bn * Fin;
    for (int f = 0; f < Fin; f++) {
        float4 a = ax[f];
        cacc(zf, a, Wxz[f * Hh + h]);
        cacc(rf, a, Wxr[f * Hh + h]);
        cacc(gf, a, Wxh[f * Hh + h]);
    }
    const float4* ah = g_AHf + bn * Hh;
    for (int j = 0; j < Hh; j++) {
        float4 a = ah[j];
        cacc(zf, a, Whz[j * Hh + h]);
        cacc(rf, a, Whr[j * Hh + h]);
    }
    float zt[4], rt[4], rh[4];
    ifft4(zf, zt);
    ifft4(rf, rt);
    const float* hs = hbuf(hsel);
    const float* bz = bias + (0 * Hh + h) * Rr;
    const float* br = bias + (1 * Hh + h) * Rr;
    #pragma unroll
    for (int r = 0; r < 4; r++) {
        float z = 1.f / (1.f + expf(-(zt[r] + bz[r])));
        g_Z[idx * 4 + r] = z;
        float rg = 1.f / (1.f + expf(-(rt[r] + br[r])));
        rh[r] = rg * hs[idx * 4 + r];
    }
    g_RHf[idx] = fft4(rh[0], rh[1], rh[2], rh[3]);
    g_Gf[idx] = gf;
}

// Ht = tanh(ifft(G + ARHf@Whr) + bh); Hnew = Z*Hs + (1-Z)*Ht
__global__ void k_final(int whr, const float* __restrict__ bias, int hsel, int hdst,
                        float* __restrict__ outp, int t) {
    int idx = blockIdx.x * blockDim.x + threadIdx.x;
    if (idx >= BNH) return;
    int h = idx % Hh;
    int bn = idx / Hh;
    const float4* Whr = g_Wf[whr];
    float4 tf = g_Gf[idx];
    const float4* ar = g_ARHf + bn * Hh;
    for (int j = 0; j < Hh; j++) cacc(tf, ar[j], Whr[j * Hh + h]);
    float tt[4];
    ifft4(tf, tt);
    const float* bh = bias + (2 * Hh + h) * Rr;
    const float* hs = hbuf(hsel);
    float* hnew = hbuf(hdst);
    int n = bn % Nn;
    int b = bn / Nn;
    float* op = outp ? (outp + (((b * Tt + t) * Nn + n) * Hh + h) * Rr) : nullptr;
    #pragma unroll
    for (int r = 0; r < 4; r++) {
        float ht = tanhf(tt[r] + bh[r]);
        float z = g_Z[idx * 4 + r];
        float hv = hs[idx * 4 + r];
        float hn = z * hv + (1.f - z) * ht;
        hnew[idx * 4 + r] = hn;
        if (op) op[r] = hn;
    }
}

__global__ void k_hlast(float* __restrict__ out) {
    int idx = blockIdx.x * blockDim.x + threadIdx.x;
    if (idx >= 2 * BNHR) return;
    float v = (idx < BNHR) ? g_h0[1][idx] : g_h1[1][idx - BNHR];
    out[OUTE + idx] = v;
}

// ---------------- host ----------------
static void run_cell(const float* xb, int xsel, int xsB, int Fin,
                     int hsel, int hdst, int w0,
                     const float* bias, float* outp, int t) {
    int nx = Bb * Nn * Fin + BNH;
    k_pre<<<(nx + 127) / 128, 128>>>(xb, xsel, xsB, Fin, hsel);
    dim3 gb((Nn + 3) / 4, Bb, 2);
    k_agg<<<gb, dim3(32, 4)>>>(0, Fin);
    k_zr<<<(BNH + 127) / 128, 128>>>(Fin, w0 + 0, w0 + 1, w0 + 2, w0 + 3, w0 + 4, bias, hsel);
    dim3 gb2((Nn + 3) / 4, Bb, 1);
    k_agg<<<gb2, dim3(32, 4)>>>(1, Hh);
    k_final<<<(BNH + 127) / 128, 128>>>(w0 + 4, bias, hsel, hdst, outp, t);
}

extern "C" void kernel_launch(void* const* d_in, const int* in_sizes, int n_in,
                              void* d_out, int out_size) {
    const float* inputs = (const float*)d_in[0];
    const float* U      = (const float*)d_in[1];
    const float* B0p    = (const float*)d_in[7];
    const float* B1p    = (const float*)d_in[13];
    float* out = (float*)d_out;

    k_zero<<<(BNHR + 255) / 256, 256>>>();
    k_adj_raw<<<(Nn * Nn + 127) / 128, 128>>>(U);
    k_softmax<<<dim3(Nn, Rr), 256>>>();
    k_adj_fft<<<(Nn * Nn + 127) / 128, 128>>>();

    // spectral weights: {d_in idx, g_Wf idx, size}
    const int wm[10][3] = {
        {2, 0, Ff * Hh}, {3, 1, Ff * Hh}, {4, 2, Ff * Hh},
        {5, 3, Hh * Hh}, {6, 4, Hh * Hh},
        {8, 5, Hh * Hh}, {9, 6, Hh * Hh}, {10, 7, Hh * Hh},
        {11, 8, Hh * Hh}, {12, 9, Hh * Hh}
    };
    for (int i = 0; i < 10; i++) {
        k_wfft<<<(wm[i][2] + 127) / 128, 128>>>((const float*)d_in[wm[i][0]], wm[i][1], wm[i][2]);
    }

    const int xsB_in = Tt * Nn * Ff * Rr;  // batch stride inside inputs at fixed t
    const int xsB_h  = Nn * Hh * Rr;       // batch stride of hidden buffers

    // t = 0: o0 = cell0(x0, 0); o1 = cell1(o0, 0)
    run_cell(inputs, 0, xsB_in, Ff, /*hs*/0, /*dst: g_h0[0]*/1, /*w0*/0, B0p, nullptr, 0);
    run_cell(nullptr, /*x = g_h0[0]*/1, xsB_h, Hh, /*hs*/0, /*dst: g_h1[0]*/3, /*w0*/5, B1p, out, 0);

    // t >= 1: n0 = cell0(x_t, p0); n1 = cell1(p0, p1)
    for (int t = 1; t < Tt; t++) {
        int s = (t - 1) & 1, d = t & 1;
        run_cell(inputs + t * Nn * Ff * Rr, 0, xsB_in, Ff,
                 /*hs: g_h0[s]*/1 + s, /*dst: g_h0[d]*/1 + d, 0, B0p, nullptr, t);
        run_cell(nullptr, /*x: g_h0[s]*/1 + s, xsB_h, Hh,
                 /*hs: g_h1[s]*/3 + s, /*dst: g_h1[d]*/3 + d, 5, B1p, out, t);
    }

    // h_last = [g_h0[1], g_h1[1]]  (T-1 = 7 -> parity 1)
    k_hlast<<<(2 * BNHR + 255) / 256, 256>>>(out);
}

// round 4
// speedup vs baseline: 2.0136x; 2.0136x over previous
#include <cuda_runtime.h>
#include <math.h>

#define Bb 32
#define Tt 8
#define Nn 150
#define Ff 16
#define Hh 32
#define Rr 4
#define Ee 16
#define NT 10
#define NTILES (Nn/NT)   // 15

#define BNH  (Bb*Nn*Hh)
#define BNHR (BNH*Rr)
#define OUTE (Bb*Tt*Nn*Hh*Rr)

// ---------------- device state (allocation-free scratch) ----------------
__device__ float4 g_Af[Nn*Nn];            // spectral adjacency
__device__ float  g_adj[Nn*Nn*Rr];        // time-domain adjacency (relu->softmax)
__device__ float4 g_Wf[10][Hh*Hh];        // spectral weights (layer0: 0..4, layer1: 5..9)
__device__ float4 g_XfAll[Tt*Bb*Nn*Ff];   // spectral inputs, all timesteps [t][b][n][f]
__device__ float4 g_h0f[2][BNH];          // spectral hidden, layer0 double buffer
__device__ float4 g_h1f[2][BNH];
__device__ float  g_h0[2][BNHR];          // time-domain hidden
__device__ float  g_h1[2][BNHR];
__device__ float  g_zb[BNHR];             // zeros (time)
__device__ float4 g_zbf[BNH];             // zeros (spectral)
__device__ float  g_Zg[2][BNHR];          // Z gate per layer
__device__ float4 g_RHf[2][BNH];          // fft(R*Hs) per layer
__device__ float4 g_Gf[2][BNH];           // spectral AX@Wxh stash per layer

// ---------------- 4-point FFT helpers (jnp.fft convention) ----------------
// planes: (X0, Re X1, Im X1, X2); X1 = x0 - i x1 - x2 + i x3
__device__ __forceinline__ float4 fft4(float x0, float x1, float x2, float x3) {
    return make_float4(x0 + x1 + x2 + x3, x0 - x2, x3 - x1, x0 - x1 + x2 - x3);
}
__device__ __forceinline__ void ifft4(float4 s, float* x) {
    x[0] = 0.25f * (s.x + 2.f * s.y + s.w);
    x[1] = 0.25f * (s.x - 2.f * s.z - s.w);
    x[2] = 0.25f * (s.x - 2.f * s.y + s.w);
    x[3] = 0.25f * (s.x + 2.f * s.z - s.w);
}
__device__ __forceinline__ void cacc(float4& o, float4 a, float4 x) {
    o.x += a.x * x.x;
    o.y += a.y * x.y - a.z * x.z;
    o.z += a.y * x.z + a.z * x.y;
    o.w += a.w * x.w;
}
__device__ __forceinline__ float4 f4add(float4 a, float4 b) {
    return make_float4(a.x + b.x, a.y + b.y, a.z + b.z, a.w + b.w);
}
__device__ __forceinline__ float sigm(float v) { return 1.f / (1.f + expf(-v)); }

// ---------------- precompute kernels ----------------
__global__ void k_init() {
    int i = blockIdx.x * blockDim.x + threadIdx.x;
    if (i < BNH) {
        g_zbf[i] = make_float4(0.f, 0.f, 0.f, 0.f);
        ((float4*)g_zb)[i] = make_float4(0.f, 0.f, 0.f, 0.f);
    }
}

__global__ void k_adj_raw(const float* __restrict__ U) {
    int idx = blockIdx.x * blockDim.x + threadIdx.x;
    if (idx >= Nn * Nn) return;
    int n = idx / Nn, m = idx % Nn;
    float4 g = make_float4(0.f, 0.f, 0.f, 0.f);
    for (int e = 0; e < Ee; e++) {
        const float* un = U + (n * Ee + e) * Rr;
        const float* um = U + (m * Ee + e) * Rr;
        float4 a = fft4(un[0], un[1], un[2], un[3]);
        float4 b = fft4(um[0], um[1], um[2], um[3]);
        cacc(g, a, b);
    }
    float x[4];
    ifft4(g, x);
    #pragma unroll
    for (int r = 0; r < 4; r++) g_adj[idx * 4 + r] = fmaxf(x[r], 0.f);
}

__global__ void k_softmax() {
    int n = blockIdx.x, r = blockIdx.y;
    int tid = threadIdx.x;
    __shared__ float red[256];
    float v = (tid < Nn) ? g_adj[(n * Nn + tid) * Rr + r] : -1e30f;
    red[tid] = v;
    __syncthreads();
    for (int s = 128; s > 0; s >>= 1) {
        if (tid < s) red[tid] = fmaxf(red[tid], red[tid + s]);
        __syncthreads();
    }
    float mx = red[0];
    __syncthreads();
    float e = (tid < Nn) ? expf(v - mx) : 0.f;
    red[tid] = e;
    __syncthreads();
    for (int s = 128; s > 0; s >>= 1) {
        if (tid < s) red[tid] += red[tid + s];
        __syncthreads();
    }
    float inv = 1.f / red[0];
    if (tid < Nn) g_adj[(n * Nn + tid) * Rr + r] = e * inv;
}

__global__ void k_adj_fft() {
    int idx = blockIdx.x * blockDim.x + threadIdx.x;
    if (idx >= Nn * Nn) return;
    const float* a = g_adj + idx * 4;
    g_Af[idx] = fft4(a[0], a[1], a[2], a[3]);
}

__global__ void k_wfft_all(const float* p0, const float* p1, const float* p2,
                           const float* p3, const float* p4, const float* p5,
                           const float* p6, const float* p7, const float* p8,
                           const float* p9) {
    int idx = blockIdx.x * blockDim.x + threadIdx.x;
    const int small = Ff * Hh;            // 512
    const int big = Hh * Hh;              // 1024
    const int total = 3 * small + 7 * big;
    if (idx >= total) return;
    int wi, off;
    if (idx < 3 * small) { wi = idx / small; off = idx % small; }
    else { int j = idx - 3 * small; wi = 3 + j / big; off = j % big; }
    const float* ps[10] = {p0, p1, p2, p3, p4, p5, p6, p7, p8, p9};
    const float* w = ps[wi] + off * Rr;
    g_Wf[wi][off] = fft4(w[0], w[1], w[2], w[3]);
}

__global__ void k_xfft(const float* __restrict__ inputs) {
    int idx = blockIdx.x * blockDim.x + threadIdx.x;
    if (idx >= Tt * Bb * Nn * Ff) return;
    int f = idx % Ff;
    int n = (idx / Ff) % Nn;
    int b = (idx / (Ff * Nn)) % Bb;
    int t = idx / (Ff * Nn * Bb);
    const float* p = inputs + ((((size_t)b * Tt + t) * Nn + n) * Ff + f) * Rr;
    g_XfAll[idx] = fft4(p[0], p[1], p[2], p[3]);
}

// ---------------- fused cell kernels ----------------
struct S1Args {
    const float4 *Xf, *Hf;
    const float *hs;
    const float4 *Wz, *Wr, *Wh, *Uz, *Ur;
    const float *bias;
    float *Z;
    float4 *RHf, *Gf;
    int Fin;
};

__global__ void __launch_bounds__(64) k_stage1(S1Args A0, S1Args A1) {
    const S1Args a = (blockIdx.z == 0) ? A0 : A1;
    __shared__ float4 s_Af[NT * Nn];
    __shared__ float4 s_AX[NT][Hh + Hh];  // max C = 64 channels
    const int tid = threadIdx.x;
    const int b = blockIdx.y;
    const int n0 = blockIdx.x * NT;

    for (int i = tid; i < NT * Nn; i += 64)
        s_Af[i] = g_Af[(n0 + i / Nn) * Nn + (i % Nn)];
    __syncthreads();

    // Phase A: aggregate over nodes for this thread's channel
    const int C = a.Fin + Hh;
    float4 acc[NT];
    #pragma unroll
    for (int j = 0; j < NT; j++) acc[j] = make_float4(0.f, 0.f, 0.f, 0.f);
    if (tid < C) {
        const float4* in;
        int stride;
        if (tid < a.Fin) { in = a.Xf + b * Nn * a.Fin + tid; stride = a.Fin; }
        else             { in = a.Hf + b * Nn * Hh + (tid - a.Fin); stride = Hh; }
        #pragma unroll 2
        for (int m = 0; m < Nn; m++) {
            float4 x = in[m * stride];
            #pragma unroll
            for (int j = 0; j < NT; j++) cacc(acc[j], s_Af[j * Nn + m], x);
        }
        #pragma unroll
        for (int j = 0; j < NT; j++) s_AX[j][tid] = acc[j];
    }
    __syncthreads();

    // Phase B: gate transforms. thread = (h, g); handles n_sub = g*5..g*5+4
    const int h = tid & 31, g = tid >> 5;
    float4 zf[5], rf[5], gf[5];
    #pragma unroll
    for (int k = 0; k < 5; k++) {
        zf[k] = make_float4(0.f, 0.f, 0.f, 0.f);
        rf[k] = zf[k]; gf[k] = zf[k];
    }
    for (int f = 0; f < a.Fin; f++) {
        float4 wz = a.Wz[f * Hh + h], wr = a.Wr[f * Hh + h], wh = a.Wh[f * Hh + h];
        #pragma unroll
        for (int k = 0; k < 5; k++) {
            float4 ax = s_AX[g * 5 + k][f];
            cacc(zf[k], ax, wz); cacc(rf[k], ax, wr); cacc(gf[k], ax, wh);
        }
    }
    for (int j = 0; j < Hh; j++) {
        float4 uz = a.Uz[j * Hh + h], ur = a.Ur[j * Hh + h];
        #pragma unroll
        for (int k = 0; k < 5; k++) {
            float4 ah = s_AX[g * 5 + k][a.Fin + j];
            cacc(zf[k], ah, uz); cacc(rf[k], ah, ur);
        }
    }
    const float4 bz = ((const float4*)a.bias)[0 * Hh + h];
    const float4 br = ((const float4*)a.bias)[1 * Hh + h];
    #pragma unroll
    for (int k = 0; k < 5; k++) {
        int n = n0 + g * 5 + k;
        int idx = (b * Nn + n) * Hh + h;
        float zt[4], rt[4], rh[4];
        ifft4(zf[k], zt);
        ifft4(rf[k], rt);
        float4 hv = ((const float4*)a.hs)[idx];
        float4 zo = make_float4(sigm(zt[0] + bz.x), sigm(zt[1] + bz.y),
                                sigm(zt[2] + bz.z), sigm(zt[3] + bz.w));
        ((float4*)a.Z)[idx] = zo;
        rh[0] = sigm(rt[0] + br.x) * hv.x;
        rh[1] = sigm(rt[1] + br.y) * hv.y;
        rh[2] = sigm(rt[2] + br.z) * hv.z;
        rh[3] = sigm(rt[3] + br.w) * hv.w;
        a.RHf[idx] = fft4(rh[0], rh[1], rh[2], rh[3]);
        a.Gf[idx] = gf[k];
    }
}

struct S2Args {
    const float4 *RHf, *Gf;
    const float *Z, *hs;
    const float4 *Ur;
    const float *bias;
    float *hnew;
    float4 *Hfnew;
    float *out;   // nullptr for layer0
};

__global__ void __launch_bounds__(64) k_stage2(S2Args A0, S2Args A1, int t) {
    const S2Args a = (blockIdx.z == 0) ? A0 : A1;
    __shared__ float4 s_Af[NT * Nn];
    __shared__ float4 s_AR[NT][Hh];
    const int tid = threadIdx.x;
    const int b = blockIdx.y;
    const int n0 = blockIdx.x * NT;

    for (int i = tid; i < NT * Nn; i += 64)
        s_Af[i] = g_Af[(n0 + i / Nn) * Nn + (i % Nn)];
    __syncthreads();

    // Phase A: aggregate RHf; thread = (c, half), each half covers 75 m's
    const int c = tid & 31, half = tid >> 5;
    float4 acc[NT];
    #pragma unroll
    for (int j = 0; j < NT; j++) acc[j] = make_float4(0.f, 0.f, 0.f, 0.f);
    const float4* in = a.RHf + b * Nn * Hh + c;
    const int m0 = half * (Nn / 2);
    #pragma unroll 2
    for (int m = m0; m < m0 + Nn / 2; m++) {
        float4 x = in[m * Hh];
        #pragma unroll
        for (int j = 0; j < NT; j++) cacc(acc[j], s_Af[j * Nn + m], x);
    }
    if (half == 0) {
        #pragma unroll
        for (int j = 0; j < NT; j++) s_AR[j][c] = acc[j];
    }
    __syncthreads();
    if (half == 1) {
        #pragma unroll
        for (int j = 0; j < NT; j++) s_AR[j][c] = f4add(s_AR[j][c], acc[j]);
    }
    __syncthreads();

    // Phase B: candidate + blend
    const int h = tid & 31, g = tid >> 5;
    float4 tf[5];
    #pragma unroll
    for (int k = 0; k < 5; k++) tf[k] = a.Gf[(b * Nn + n0 + g * 5 + k) * Hh + h];
    for (int j = 0; j < Hh; j++) {
        float4 ur = a.Ur[j * Hh + h];
        #pragma unroll
        for (int k = 0; k < 5; k++) cacc(tf[k], s_AR[g * 5 + k][j], ur);
    }
    const float4 bh = ((const float4*)a.bias)[2 * Hh + h];
    #pragma unroll
    for (int k = 0; k < 5; k++) {
        int n = n0 + g * 5 + k;
        int idx = (b * Nn + n) * Hh + h;
        float tt[4];
        ifft4(tf[k], tt);
        float4 z = ((const float4*)a.Z)[idx];
        float4 hv = ((const float4*)a.hs)[idx];
        float4 hn;
        hn.x = z.x * hv.x + (1.f - z.x) * tanhf(tt[0] + bh.x);
        hn.y = z.y * hv.y + (1.f - z.y) * tanhf(tt[1] + bh.y);
        hn.z = z.z * hv.z + (1.f - z.z) * tanhf(tt[2] + bh.z);
        hn.w = z.w * hv.w + (1.f - z.w) * tanhf(tt[3] + bh.w);
        ((float4*)a.hnew)[idx] = hn;
        a.Hfnew[idx] = fft4(hn.x, hn.y, hn.z, hn.w);
        if (a.out) ((float4*)a.out)[((b * Tt + t) * Nn + n) * Hh + h] = hn;
    }
}

__global__ void k_hlast(float* __restrict__ out) {
    int idx = blockIdx.x * blockDim.x + threadIdx.x;
    if (idx >= 2 * BNHR) return;
    float v = (idx < BNHR) ? g_h0[1][idx] : g_h1[1][idx - BNHR];
    out[OUTE + idx] = v;
}

// ---------------- host ----------------
extern "C" void kernel_launch(void* const* d_in, const int* in_sizes, int n_in,
                              void* d_out, int out_size) {
    const float* inputs = (const float*)d_in[0];
    const float* U      = (const float*)d_in[1];
    const float* B0p    = (const float*)d_in[7];
    const float* B1p    = (const float*)d_in[13];
    float* out = (float*)d_out;

    void *pWf, *pXf, *ph0f, *ph1f, *ph0, *ph1, *pzb, *pzbf, *pZ, *pRH, *pG;
    cudaGetSymbolAddress(&pWf,  g_Wf);
    cudaGetSymbolAddress(&pXf,  g_XfAll);
    cudaGetSymbolAddress(&ph0f, g_h0f);
    cudaGetSymbolAddress(&ph1f, g_h1f);
    cudaGetSymbolAddress(&ph0,  g_h0);
    cudaGetSymbolAddress(&ph1,  g_h1);
    cudaGetSymbolAddress(&pzb,  g_zb);
    cudaGetSymbolAddress(&pzbf, g_zbf);
    cudaGetSymbolAddress(&pZ,   g_Zg);
    cudaGetSymbolAddress(&pRH,  g_RHf);
    cudaGetSymbolAddress(&pG,   g_Gf);

    float4* Wfp   = (float4*)pWf;
    float4* XfAll = (float4*)pXf;
    float4* h0f[2] = {(float4*)ph0f, (float4*)ph0f + BNH};
    float4* h1f[2] = {(float4*)ph1f, (float4*)ph1f + BNH};
    float*  h0[2]  = {(float*)ph0, (float*)ph0 + BNHR};
    float*  h1[2]  = {(float*)ph1, (float*)ph1 + BNHR};
    float*  zb     = (float*)pzb;
    float4* zbf    = (float4*)pzbf;
    float*  Zl[2]  = {(float*)pZ, (float*)pZ + BNHR};
    float4* RHl[2] = {(float4*)pRH, (float4*)pRH + BNH};
    float4* Gl[2]  = {(float4*)pG, (float4*)pG + BNH};

    k_init<<<(BNH + 255) / 256, 256>>>();
    k_adj_raw<<<(Nn * Nn + 127) / 128, 128>>>(U);
    k_softmax<<<dim3(Nn, Rr), 256>>>();
    k_adj_fft<<<(Nn * Nn + 127) / 128, 128>>>();
    {
        int wtot = 3 * Ff * Hh + 7 * Hh * Hh;
        k_wfft_all<<<(wtot + 127) / 128, 128>>>(
            (const float*)d_in[2], (const float*)d_in[3], (const float*)d_in[4],
            (const float*)d_in[5], (const float*)d_in[6],
            (const float*)d_in[8], (const float*)d_in[9], (const float*)d_in[10],
            (const float*)d_in[11], (const float*)d_in[12]);
    }
    k_xfft<<<(Tt * Bb * Nn * Ff + 255) / 256, 256>>>(inputs);

    auto mkS1 = [&](int L, int t, int s) -> S1Args {
        S1Args a;
        if (L == 0) {
            a.Xf = XfAll + (size_t)t * Bb * Nn * Ff;
            a.Fin = Ff;
            a.Hf = (t == 0) ? zbf : h0f[s];
            a.hs = (t == 0) ? zb : h0[s];
            a.Wz = Wfp + 0 * 1024; a.Wr = Wfp + 1 * 1024; a.Wh = Wfp + 2 * 1024;
            a.Uz = Wfp + 3 * 1024; a.Ur = Wfp + 4 * 1024;
            a.bias = B0p; a.Z = Zl[0]; a.RHf = RHl[0]; a.Gf = Gl[0];
        } else {
            a.Xf = h0f[s];
            a.Fin = Hh;
            a.Hf = (t == 0) ? zbf : h1f[s];
            a.hs = (t == 0) ? zb : h1[s];
            a.Wz = Wfp + 5 * 1024; a.Wr = Wfp + 6 * 1024; a.Wh = Wfp + 7 * 1024;
            a.Uz = Wfp + 8 * 1024; a.Ur = Wfp + 9 * 1024;
            a.bias = B1p; a.Z = Zl[1]; a.RHf = RHl[1]; a.Gf = Gl[1];
        }
        return a;
    };
    auto mkS2 = [&](int L, int t, int s, int d) -> S2Args {
        S2Args a;
        if (L == 0) {
            a.RHf = RHl[0]; a.Gf = Gl[0]; a.Z = Zl[0];
            a.hs = (t == 0) ? zb : h0[s];
            a.Ur = Wfp + 4 * 1024; a.bias = B0p;
            a.hnew = h0[d]; a.Hfnew = h0f[d]; a.out = nullptr;
        } else {
            a.RHf = RHl[1]; a.Gf = Gl[1]; a.Z = Zl[1];
            a.hs = (t == 0) ? zb : h1[s];
            a.Ur = Wfp + 9 * 1024; a.bias = B1p;
            a.hnew = h1[d]; a.Hfnew = h1f[d]; a.out = out;
        }
        return a;
    };

    const dim3 blk(64);

    // t = 0: layer1 consumes the CURRENT layer0 output -> sequential
    { S1Args a = mkS1(0, 0, 0);       k_stage1<<<dim3(NTILES, Bb, 1), blk>>>(a, a); }
    { S2Args a = mkS2(0, 0, 0, 0);    k_stage2<<<dim3(NTILES, Bb, 1), blk>>>(a, a, 0); }
    { S1Args a = mkS1(1, 0, 0);       k_stage1<<<dim3(NTILES, Bb, 1), blk>>>(a, a); }
    { S2Args a = mkS2(1, 0, 0, 0);    k_stage2<<<dim3(NTILES, Bb, 1), blk>>>(a, a, 0); }

    // t >= 1: layer0(t) and layer1(t) are independent -> merged launches
    for (int t = 1; t < Tt; t++) {
        int s = (t - 1) & 1, d = t & 1;
        S1Args a0 = mkS1(0, t, s), a1 = mkS1(1, t, s);
        k_stage1<<<dim3(NTILES, Bb, 2), blk>>>(a0, a1);
        S2Args c0 = mkS2(0, t, s, d), c1 = mkS2(1, t, s, d);
        k_stage2<<<dim3(NTILES, Bb, 2), blk>>>(c0, c1, t);
    }

    // h_last = [h0 final, h1 final]; t=7 -> buffer parity 1
    k_hlast<<<(2 * BNHR + 255) / 256, 256>>>(out);
}